// round 14
// baseline (speedup 1.0000x reference)
#include <cuda_runtime.h>
#include <cuda_fp16.h>
#include <math.h>
#include <stdint.h>

#define N_SEQ 512
#define N_RES 384
#define C_M   256
#define C_OUT 32
#define C_Z   128
#define BC    (N_RES * C_OUT)     /* 12288  (b,c) flattened */
#define NPAIR (N_RES * N_RES)     /* 147456 (b,d) pairs     */
#define KCE   (C_OUT * C_OUT)     /* 1024   (c,e) flattened */

// ---------------- scratch (device globals; no allocation allowed) ----------
__device__ float g_ninv[NPAIR];
// fp16 K-major operands: [bc|de][a]  (written directly by ln_proj_mma)
__device__ __align__(128) __half g_Lh[(size_t)BC * N_SEQ];
__device__ __align__(128) __half g_Rh[(size_t)BC * N_SEQ];
// inter, PERMUTED [(b,d),(c,e)], single fp16
__device__ __align__(128) __half g_iPhi[(size_t)NPAIR * KCE];  // 302 MB
// W transposed: [f][ce], single fp16
__device__ __align__(128) __half g_Wt[(size_t)C_Z * KCE];
// projection weights, transposed: [og 64][k 256]
__device__ __align__(128) __half g_PwT[64 * C_M];

// ======================= PTX helpers (baseline sm_80 features) =============
__device__ __forceinline__ uint32_t smem_u32(const void* p) {
    uint32_t a;
    asm("{ .reg .u64 t; cvta.to.shared.u64 t, %1; cvt.u32.u64 %0, t; }"
        : "=r"(a) : "l"(p));
    return a;
}
#define LDSM_X4(r, addr) \
    asm volatile("ldmatrix.sync.aligned.m8n8.x4.shared.b16 {%0,%1,%2,%3}, [%4];" \
                 : "=r"((r)[0]), "=r"((r)[1]), "=r"((r)[2]), "=r"((r)[3]) \
                 : "r"(addr))
#define MMA_F16(d, a, b0, b1) \
    asm volatile("mma.sync.aligned.m16n8k16.row.col.f32.f16.f16.f32 " \
                 "{%0,%1,%2,%3},{%4,%5,%6,%7},{%8,%9},{%0,%1,%2,%3};" \
                 : "+f"((d)[0]), "+f"((d)[1]), "+f"((d)[2]), "+f"((d)[3]) \
                 : "r"((a)[0]), "r"((a)[1]), "r"((a)[2]), "r"((a)[3]), \
                   "r"(b0), "r"(b1))
#define CP_ASYNC16(dst, src) \
    asm volatile("cp.async.cg.shared.global [%0], [%1], 16;" \
                 :: "r"(dst), "l"(src) : "memory")
#define CP_COMMIT() asm volatile("cp.async.commit_group;" ::: "memory")
#define CP_WAIT(n)  asm volatile("cp.async.wait_group %0;" :: "n"(n) : "memory")

// XOR swizzle on linear chunk id L (= m*4 + c), any number of rows.
__device__ __forceinline__ uint32_t swzL(int L) {
    return (uint32_t)(((L >> 3) << 7) + ((((L & 7) ^ ((L >> 3) & 7))) << 4));
}
__device__ __forceinline__ uint32_t swz(int m, int c) { return swzL(m * 4 + c); }

__device__ __forceinline__ uint32_t pack_h2(float a, float b) {
    __half2 p = __halves2half2(__float2half_rn(a), __float2half_rn(b));
    return *(uint32_t*)&p;
}

// ---------------- Kernel 1: LN + projection via tensor cores ---------------
#define YT_STRIDE 4112
#define LNP_YHI 0
#define LNP_YLO 32896
#define LNP_W   65792
#define LNP_SMEM 98688

__global__ __launch_bounds__(256, 2) void ln_proj_mma(
    const float* __restrict__ act, const float* __restrict__ mask,
    const float* __restrict__ ln_scale, const float* __restrict__ ln_offset,
    const float* __restrict__ left_b, const float* __restrict__ right_b)
{
    extern __shared__ __align__(128) char smem[];
    uint32_t sb = smem_u32(smem);
    int tid = threadIdx.x, lane = tid & 31, wid = tid >> 5;
    int b  = blockIdx.x % N_RES;
    int a0 = (blockIdx.x / N_RES) * 64;

    #pragma unroll
    for (int i = 0; i < 8; i++) {
        int q = tid * 8 + i;
        int row = q >> 5, c32 = q & 31;
        CP_ASYNC16(sb + LNP_W + (c32 >> 2) * YT_STRIDE + swz(row, c32 & 3),
                   g_PwT + row * C_M + c32 * 8);
    }
    CP_COMMIT();

    for (int it = 0; it < 8; it++) {
        int rl = wid + it * 8;
        size_t row = (size_t)(a0 + rl) * N_RES + b;
        const float4* ap = (const float4*)(act + row * C_M + lane * 8);
        float4 x0 = ap[0], x1 = ap[1];
        float s  = x0.x + x0.y + x0.z + x0.w + x1.x + x1.y + x1.z + x1.w;
        float s2 = x0.x*x0.x + x0.y*x0.y + x0.z*x0.z + x0.w*x0.w
                 + x1.x*x1.x + x1.y*x1.y + x1.z*x1.z + x1.w*x1.w;
        #pragma unroll
        for (int o = 16; o > 0; o >>= 1) {
            s  += __shfl_xor_sync(0xffffffffu, s, o);
            s2 += __shfl_xor_sync(0xffffffffu, s2, o);
        }
        float mu = s * (1.0f / C_M);
        float var = s2 * (1.0f / C_M) - mu * mu;
        float rstd = rsqrtf(var + 1e-5f);
        float4 sc0 = *(const float4*)(ln_scale + lane * 8);
        float4 sc1 = *(const float4*)(ln_scale + lane * 8 + 4);
        float4 of0 = *(const float4*)(ln_offset + lane * 8);
        float4 of1 = *(const float4*)(ln_offset + lane * 8 + 4);
        float y[8];
        y[0] = (x0.x - mu) * rstd * sc0.x + of0.x;
        y[1] = (x0.y - mu) * rstd * sc0.y + of0.y;
        y[2] = (x0.z - mu) * rstd * sc0.z + of0.z;
        y[3] = (x0.w - mu) * rstd * sc0.w + of0.w;
        y[4] = (x1.x - mu) * rstd * sc1.x + of1.x;
        y[5] = (x1.y - mu) * rstd * sc1.y + of1.y;
        y[6] = (x1.z - mu) * rstd * sc1.z + of1.z;
        y[7] = (x1.w - mu) * rstd * sc1.w + of1.w;
        float hi[8];
        uint4 vh, vl;
        #pragma unroll
        for (int j = 0; j < 8; j++)
            hi[j] = __half2float(__float2half_rn(y[j]));
        vh.x = pack_h2(y[0], y[1]); vh.y = pack_h2(y[2], y[3]);
        vh.z = pack_h2(y[4], y[5]); vh.w = pack_h2(y[6], y[7]);
        vl.x = pack_h2(y[0]-hi[0], y[1]-hi[1]); vl.y = pack_h2(y[2]-hi[2], y[3]-hi[3]);
        vl.z = pack_h2(y[4]-hi[4], y[5]-hi[5]); vl.w = pack_h2(y[6]-hi[6], y[7]-hi[7]);
        uint32_t off = (lane >> 2) * YT_STRIDE + swz(rl, lane & 3);
        *(uint4*)(smem + LNP_YHI + off) = vh;
        *(uint4*)(smem + LNP_YLO + off) = vl;
    }
    CP_WAIT(0);
    __syncthreads();

    int m2 = wid & 3, n32 = wid >> 2;
    uint32_t aoff[2], boff[2][2];
    #pragma unroll
    for (int ks = 0; ks < 2; ks++) {
        aoff[ks] = swz(m2 * 16 + (lane & 15), ks * 2 + (lane >> 4));
        #pragma unroll
        for (int n2 = 0; n2 < 2; n2++)
            boff[n2][ks] = swz(n32 * 32 + n2 * 16 + (lane & 15), ks * 2 + (lane >> 4));
    }
    float acc[4][4];
    #pragma unroll
    for (int a = 0; a < 4; a++)
        #pragma unroll
        for (int c = 0; c < 4; c++) acc[a][c] = 0.f;

    #pragma unroll
    for (int kc = 0; kc < 8; kc++) {
        uint32_t yh = sb + LNP_YHI + kc * YT_STRIDE;
        uint32_t yl = sb + LNP_YLO + kc * YT_STRIDE;
        uint32_t wb = sb + LNP_W   + kc * YT_STRIDE;
        #pragma unroll
        for (int ks = 0; ks < 2; ks++) {
            uint32_t ah[4], al[4], b0[4], b1[4];
            LDSM_X4(ah, yh + aoff[ks]);
            LDSM_X4(al, yl + aoff[ks]);
            LDSM_X4(b0, wb + boff[0][ks]);
            LDSM_X4(b1, wb + boff[1][ks]);
            #pragma unroll
            for (int nt = 0; nt < 4; nt++) {
                uint32_t* bp = (nt < 2) ? b0 : b1;
                MMA_F16(acc[nt], ah, bp[nt & 1], bp[(nt & 1) + 2]);
            }
            #pragma unroll
            for (int nt = 0; nt < 4; nt++) {
                uint32_t* bp = (nt < 2) ? b0 : b1;
                MMA_F16(acc[nt], al, bp[nt & 1], bp[(nt & 1) + 2]);
            }
        }
    }

    __half* dstb = n32 ? g_Rh : g_Lh;
    #pragma unroll
    for (int nt = 0; nt < 4; nt++) {
        int ogl = nt * 8 + (lane & 3) * 2;
        float b0v = n32 ? right_b[ogl] : left_b[ogl];
        float b1v = n32 ? right_b[ogl + 1] : left_b[ogl + 1];
        #pragma unroll
        for (int h = 0; h < 2; h++) {
            int a = a0 + m2 * 16 + (lane >> 2) + h * 8;
            float mv = mask[(size_t)a * N_RES + b];
            float vx = mv * (acc[nt][h * 2 + 0] + b0v);
            float vy = mv * (acc[nt][h * 2 + 1] + b1v);
            dstb[(size_t)(b * 32 + ogl)     * N_SEQ + a] = __float2half_rn(vx);
            dstb[(size_t)(b * 32 + ogl + 1) * N_SEQ + a] = __float2half_rn(vy);
        }
    }
}

// ------ prep: norm recip (0..575) + W transpose (576..703) + PwT (704) -----
__global__ __launch_bounds__(256) void prep_kernel(
    const float* __restrict__ mask, const float* __restrict__ W,
    const float* __restrict__ left_w, const float* __restrict__ right_w)
{
    if (blockIdx.x < 576) {
        int m = blockIdx.x * 256 + threadIdx.x;
        int b = m / N_RES, d = m % N_RES;
        float s = 0.f;
        for (int a = 0; a < N_SEQ; a++)
            s += mask[a * N_RES + b] * mask[a * N_RES + d];
        g_ninv[m] = 1.0f / (1e-3f + s);
    } else if (blockIdx.x < 704) {
        __shared__ float t[32][33];
        int bb = blockIdx.x - 576;
        int k0 = (bb & 31) * 32;
        int f0 = (bb >> 5) * 32;
        for (int i = threadIdx.x; i < 1024; i += 256) {
            int r = i >> 5, c = i & 31;
            t[r][c] = W[(size_t)(k0 + r) * C_Z + f0 + c];
        }
        __syncthreads();
        for (int i = threadIdx.x; i < 1024; i += 256) {
            int r = i >> 5, c = i & 31;
            g_Wt[(size_t)(f0 + r) * KCE + k0 + c] = __float2half_rn(t[c][r]);
        }
    } else {
        for (int i = 0; i < 64; i++) {
            int og = i, k = threadIdx.x;
            float v = (og < 32) ? left_w[k * C_OUT + og]
                                : right_w[k * C_OUT + og - 32];
            g_PwT[og * C_M + k] = __float2half_rn(v);
        }
    }
}

// ============ GEMM1: 128(bc) x 256(de) CTA tile, 8 warps @ 64x64 ===========
#define G1_A_B   8192                    /* A tile: 128 rows x 64B */
#define G1_B_B   16384                   /* B tile: 256 rows x 64B */
#define G1_STAGE 24576
#define G1_SMEM  73728                   /* 3 stages; 64KB epi staging reuses */

__global__ __launch_bounds__(256, 1) void gemm1_mma()
{
    extern __shared__ __align__(128) char smem[];
    uint32_t sb = smem_u32(smem);
    int tid = threadIdx.x, lane = tid & 31, wid = tid >> 5;
    int i0 = blockIdx.y * 128;     // bc (M)
    int j0 = blockIdx.x * 256;     // de (N)
    int m_base = (wid & 1) * 64, n_base = (wid >> 1) * 64;

    const __half* Ab = g_Lh + (size_t)i0 * N_SEQ;
    const __half* Bb = g_Rh + (size_t)j0 * N_SEQ;

    // cp.async: 1536 chunks/stage, 6 per thread. i<2 -> A, i>=2 -> B.
    uint32_t sdst[6]; const __half* gsrc[6];
    #pragma unroll
    for (int i = 0; i < 6; i++) {
        int ch = tid + (i << 8);
        if (i < 2) {
            sdst[i] = swzL(ch);                                  // A region
            gsrc[i] = Ab + (size_t)(ch >> 2) * N_SEQ + (ch & 3) * 8;
        } else {
            int L = ch - 512;
            sdst[i] = (uint32_t)G1_A_B + swzL(L);                // B region
            gsrc[i] = Bb + (size_t)(L >> 2) * N_SEQ + (L & 3) * 8;
        }
    }

    uint32_t aoff[4][2], boff[4][2];
    #pragma unroll
    for (int mt = 0; mt < 4; mt++)
        #pragma unroll
        for (int ks = 0; ks < 2; ks++)
            aoff[mt][ks] = swz(m_base + mt * 16 + (lane & 15), ks * 2 + (lane >> 4));
    #pragma unroll
    for (int n2 = 0; n2 < 4; n2++)
        #pragma unroll
        for (int ks = 0; ks < 2; ks++)
            boff[n2][ks] = (uint32_t)G1_A_B +
                swz(n_base + n2 * 16 + (lane & 15), ks * 2 + (lane >> 4));

    float acc[4][8][4];
    #pragma unroll
    for (int a = 0; a < 4; a++)
        #pragma unroll
        for (int b = 0; b < 8; b++)
            #pragma unroll
            for (int c = 0; c < 4; c++) acc[a][b][c] = 0.f;

    #pragma unroll
    for (int s = 0; s < 2; s++) {
        #pragma unroll
        for (int i = 0; i < 6; i++)
            CP_ASYNC16(sb + s * G1_STAGE + sdst[i], gsrc[i] + s * 32);
        CP_COMMIT();
    }

    for (int kt = 0; kt < 16; kt++) {
        CP_WAIT(1);
        __syncthreads();
        if (kt + 2 < 16) {
            uint32_t so = (uint32_t)((kt + 2) % 3) * G1_STAGE;
            #pragma unroll
            for (int i = 0; i < 6; i++)
                CP_ASYNC16(sb + so + sdst[i], gsrc[i] + (kt + 2) * 32);
        }
        CP_COMMIT();
        uint32_t stb = sb + (uint32_t)(kt % 3) * G1_STAGE;
        #pragma unroll
        for (int ks = 0; ks < 2; ks++) {
            uint32_t ah[4][4], bh[4][4];
            #pragma unroll
            for (int mt = 0; mt < 4; mt++)
                LDSM_X4(ah[mt], stb + aoff[mt][ks]);
            #pragma unroll
            for (int n2 = 0; n2 < 4; n2++)
                LDSM_X4(bh[n2], stb + boff[n2][ks]);
            #pragma unroll
            for (int mt = 0; mt < 4; mt++)
                #pragma unroll
                for (int nt = 0; nt < 8; nt++)
                    MMA_F16(acc[mt][nt], ah[mt], bh[nt >> 1][nt & 1],
                            bh[nt >> 1][(nt & 1) + 2]);
        }
    }

    // epilogue: scatter 128x256 fp16 permuted into smem, then coalesced copy
    __syncthreads();
    int g = lane >> 2, tg = lane & 3;
    #pragma unroll
    for (int mt = 0; mt < 4; mt++) {
        #pragma unroll
        for (int h = 0; h < 2; h++) {
            int rr = m_base + mt * 16 + g + h * 8;
            int bl = rr >> 5, c = rr & 31;
            #pragma unroll
            for (int nt = 0; nt < 8; nt++) {
                int q = n_base + nt * 8 + tg * 2;
                int dl = q >> 5, e = q & 31;
                int p = bl * 8 + dl;                  // 0..31 pairs
                uint32_t off = (uint32_t)(p * 2048 + (c * 32 + e) * 2);
                *(__half2*)(smem + off) = __halves2half2(
                    __float2half_rn(acc[mt][nt][h * 2 + 0]),
                    __float2half_rn(acc[mt][nt][h * 2 + 1]));
            }
        }
    }
    __syncthreads();
    int b0 = blockIdx.y * 4, d0 = blockIdx.x * 8;
    #pragma unroll
    for (int i = 0; i < 16; i++) {
        int qc = tid + 256 * i;                       // 4096 chunks of 16B
        int p = qc >> 7, off = qc & 127;
        size_t row = (size_t)((b0 + (p >> 3)) * N_RES + d0 + (p & 7)) * KCE + off * 8;
        *(uint4*)(g_iPhi + row) = *(const uint4*)(smem + qc * 16);
    }
}

// ============ GEMM2 smem geometry ==========================================
#define TILE_B   8192
#define G2_STAGE 16384
#define G2_SMEM  49152

// ---------------- Kernel 4: GEMM2 = interP @ Wt^T + b, / norm (1-term) -----
__global__ __launch_bounds__(256, 2) void gemm2_mma(
    const float* __restrict__ ob, float* __restrict__ out)
{
    extern __shared__ __align__(128) char smem[];
    uint32_t sb = smem_u32(smem);
    int tid = threadIdx.x, lane = tid & 31, wid = tid >> 5;
    int m0 = blockIdx.x * 128;
    int m_base = (wid & 1) * 64, n_base = (wid >> 1) * 32;

    const __half* base[2] = { g_iPhi + (size_t)m0 * KCE, g_Wt };

    uint32_t soff[2]; int gofs[2];
    #pragma unroll
    for (int i = 0; i < 2; i++) {
        int ch = tid + (i << 8);
        int m = ch >> 2, c = ch & 3;
        soff[i] = swz(m, c);
        gofs[i] = m * KCE + c * 8;
    }

    uint32_t aoff[4][2], boff[2][2];
    #pragma unroll
    for (int mt = 0; mt < 4; mt++)
        #pragma unroll
        for (int ks = 0; ks < 2; ks++)
            aoff[mt][ks] = swz(m_base + mt * 16 + (lane & 15), ks * 2 + (lane >> 4));
    #pragma unroll
    for (int n2 = 0; n2 < 2; n2++)
        #pragma unroll
        for (int ks = 0; ks < 2; ks++)
            boff[n2][ks] = swz(n_base + n2 * 16 + (lane & 15), ks * 2 + (lane >> 4));

    float acc[4][4][4];
    #pragma unroll
    for (int a = 0; a < 4; a++)
        #pragma unroll
        for (int b = 0; b < 4; b++)
            #pragma unroll
            for (int c = 0; c < 4; c++) acc[a][b][c] = 0.f;

    #pragma unroll
    for (int s = 0; s < 2; s++) {
        #pragma unroll
        for (int t = 0; t < 2; t++)
            #pragma unroll
            for (int i = 0; i < 2; i++)
                CP_ASYNC16(sb + s * G2_STAGE + t * TILE_B + soff[i],
                           base[t] + gofs[i] + s * 32);
        CP_COMMIT();
    }

    for (int kt = 0; kt < 32; kt++) {
        CP_WAIT(1);
        __syncthreads();
        if (kt + 2 < 32) {
            uint32_t so = (uint32_t)((kt + 2) % 3) * G2_STAGE;
            #pragma unroll
            for (int t = 0; t < 2; t++)
                #pragma unroll
                for (int i = 0; i < 2; i++)
                    CP_ASYNC16(sb + so + t * TILE_B + soff[i],
                               base[t] + gofs[i] + (kt + 2) * 32);
        }
        CP_COMMIT();
        uint32_t stb = sb + (uint32_t)(kt % 3) * G2_STAGE;
        #pragma unroll
        for (int ks = 0; ks < 2; ks++) {
            uint32_t ah[4][4], bh[2][4];
            #pragma unroll
            for (int mt = 0; mt < 4; mt++)
                LDSM_X4(ah[mt], stb + aoff[mt][ks]);
            #pragma unroll
            for (int n2 = 0; n2 < 2; n2++)
                LDSM_X4(bh[n2], stb + TILE_B + boff[n2][ks]);
            #pragma unroll
            for (int mt = 0; mt < 4; mt++)
                #pragma unroll
                for (int nt = 0; nt < 4; nt++)
                    MMA_F16(acc[mt][nt], ah[mt], bh[nt >> 1][nt & 1],
                            bh[nt >> 1][(nt & 1) + 2]);
        }
    }

    int g = lane >> 2, tg = lane & 3;
    #pragma unroll
    for (int mt = 0; mt < 4; mt++) {
        #pragma unroll
        for (int h = 0; h < 2; h++) {
            int m = m0 + m_base + mt * 16 + g + h * 8;
            float inv = g_ninv[m];
            #pragma unroll
            for (int nt = 0; nt < 4; nt++) {
                int f = n_base + nt * 8 + tg * 2;
                float2 v;
                v.x = (acc[mt][nt][h * 2 + 0] + ob[f + 0]) * inv;
                v.y = (acc[mt][nt][h * 2 + 1] + ob[f + 1]) * inv;
                *(float2*)&out[(size_t)m * C_Z + f] = v;
            }
        }
    }
}

// ---------------------------------------------------------------------------
extern "C" void kernel_launch(void* const* d_in, const int* in_sizes, int n_in,
                              void* d_out, int out_size)
{
    const float* act       = (const float*)d_in[0];
    const float* mask      = (const float*)d_in[1];
    const float* ln_scale  = (const float*)d_in[2];
    const float* ln_offset = (const float*)d_in[3];
    const float* left_w    = (const float*)d_in[4];
    const float* left_b    = (const float*)d_in[5];
    const float* right_w   = (const float*)d_in[6];
    const float* right_b   = (const float*)d_in[7];
    const float* output_w  = (const float*)d_in[8];
    const float* output_b  = (const float*)d_in[9];
    float* out = (float*)d_out;

    cudaFuncSetAttribute(ln_proj_mma, cudaFuncAttributeMaxDynamicSharedMemorySize, LNP_SMEM);
    cudaFuncSetAttribute(gemm1_mma, cudaFuncAttributeMaxDynamicSharedMemorySize, G1_SMEM);
    cudaFuncSetAttribute(gemm2_mma, cudaFuncAttributeMaxDynamicSharedMemorySize, G2_SMEM);

    // launches: prep(1), ln_proj_mma(2), gemm1(3 = check slot-3), gemm2(4)
    prep_kernel<<<705, 256>>>(mask, output_w, left_w, right_w);
    ln_proj_mma<<<N_SEQ * N_RES / 64, 256, LNP_SMEM>>>(act, mask, ln_scale, ln_offset,
                                                       left_b, right_b);
    gemm1_mma<<<dim3(BC / 256, BC / 128), 256, G1_SMEM>>>();
    gemm2_mma<<<NPAIR / 128, 256, G2_SMEM>>>(output_b, out);
}

// round 15
// speedup vs baseline: 1.1414x; 1.1414x over previous
#include <cuda_runtime.h>
#include <cuda_fp16.h>
#include <math.h>
#include <stdint.h>

#define N_SEQ 512
#define N_RES 384
#define C_M   256
#define C_OUT 32
#define C_Z   128
#define BC    (N_RES * C_OUT)     /* 12288  (b,c) flattened */
#define NPAIR (N_RES * N_RES)     /* 147456 (b,d) pairs     */
#define KCE   (C_OUT * C_OUT)     /* 1024   (c,e) flattened */

// ---------------- scratch (device globals; no allocation allowed) ----------
__device__ float g_ninv[NPAIR];
// fp16 K-major operands: [bc|de][a]  (written directly by ln_proj_mma)
__device__ __align__(128) __half g_Lh[(size_t)BC * N_SEQ];
__device__ __align__(128) __half g_Rh[(size_t)BC * N_SEQ];
// inter, PERMUTED [(b,d),(c,e)], single fp16
__device__ __align__(128) __half g_iPhi[(size_t)NPAIR * KCE];  // 302 MB
// W transposed: [f][ce], single fp16
__device__ __align__(128) __half g_Wt[(size_t)C_Z * KCE];
// projection weights, transposed: [og 64][k 256]
__device__ __align__(128) __half g_PwT[64 * C_M];

// ======================= PTX helpers (baseline sm_80 features) =============
__device__ __forceinline__ uint32_t smem_u32(const void* p) {
    uint32_t a;
    asm("{ .reg .u64 t; cvta.to.shared.u64 t, %1; cvt.u32.u64 %0, t; }"
        : "=r"(a) : "l"(p));
    return a;
}
#define LDSM_X4(r, addr) \
    asm volatile("ldmatrix.sync.aligned.m8n8.x4.shared.b16 {%0,%1,%2,%3}, [%4];" \
                 : "=r"((r)[0]), "=r"((r)[1]), "=r"((r)[2]), "=r"((r)[3]) \
                 : "r"(addr))
#define MMA_F16(d, a, b0, b1) \
    asm volatile("mma.sync.aligned.m16n8k16.row.col.f32.f16.f16.f32 " \
                 "{%0,%1,%2,%3},{%4,%5,%6,%7},{%8,%9},{%0,%1,%2,%3};" \
                 : "+f"((d)[0]), "+f"((d)[1]), "+f"((d)[2]), "+f"((d)[3]) \
                 : "r"((a)[0]), "r"((a)[1]), "r"((a)[2]), "r"((a)[3]), \
                   "r"(b0), "r"(b1))
#define CP_ASYNC16(dst, src) \
    asm volatile("cp.async.cg.shared.global [%0], [%1], 16;" \
                 :: "r"(dst), "l"(src) : "memory")
#define CP_COMMIT() asm volatile("cp.async.commit_group;" ::: "memory")
#define CP_WAIT(n)  asm volatile("cp.async.wait_group %0;" :: "n"(n) : "memory")

// XOR swizzle: chunk (m, c) of a [<=128 rows x 4 chunks-of-16B] tile.
__device__ __forceinline__ uint32_t swz(int m, int c) {
    int L = m * 4 + c;
    return (uint32_t)(((L >> 3) << 7) + ((((L & 7) ^ ((L >> 3) & 7))) << 4));
}

__device__ __forceinline__ uint32_t pack_h2(float a, float b) {
    __half2 p = __halves2half2(__float2half_rn(a), __float2half_rn(b));
    return *(uint32_t*)&p;
}

// ---------------- Kernel 1: LN + projection via tensor cores ---------------
#define YT_STRIDE 4112
#define LNP_YHI 0
#define LNP_YLO 32896
#define LNP_W   65792
#define LNP_SMEM 98688

__global__ __launch_bounds__(256, 2) void ln_proj_mma(
    const float* __restrict__ act, const float* __restrict__ mask,
    const float* __restrict__ ln_scale, const float* __restrict__ ln_offset,
    const float* __restrict__ left_b, const float* __restrict__ right_b)
{
    extern __shared__ __align__(128) char smem[];
    uint32_t sb = smem_u32(smem);
    int tid = threadIdx.x, lane = tid & 31, wid = tid >> 5;
    int b  = blockIdx.x % N_RES;
    int a0 = (blockIdx.x / N_RES) * 64;

    #pragma unroll
    for (int i = 0; i < 8; i++) {
        int q = tid * 8 + i;
        int row = q >> 5, c32 = q & 31;
        CP_ASYNC16(sb + LNP_W + (c32 >> 2) * YT_STRIDE + swz(row, c32 & 3),
                   g_PwT + row * C_M + c32 * 8);
    }
    CP_COMMIT();

    for (int it = 0; it < 8; it++) {
        int rl = wid + it * 8;
        size_t row = (size_t)(a0 + rl) * N_RES + b;
        const float4* ap = (const float4*)(act + row * C_M + lane * 8);
        float4 x0 = ap[0], x1 = ap[1];
        float s  = x0.x + x0.y + x0.z + x0.w + x1.x + x1.y + x1.z + x1.w;
        float s2 = x0.x*x0.x + x0.y*x0.y + x0.z*x0.z + x0.w*x0.w
                 + x1.x*x1.x + x1.y*x1.y + x1.z*x1.z + x1.w*x1.w;
        #pragma unroll
        for (int o = 16; o > 0; o >>= 1) {
            s  += __shfl_xor_sync(0xffffffffu, s, o);
            s2 += __shfl_xor_sync(0xffffffffu, s2, o);
        }
        float mu = s * (1.0f / C_M);
        float var = s2 * (1.0f / C_M) - mu * mu;
        float rstd = rsqrtf(var + 1e-5f);
        float4 sc0 = *(const float4*)(ln_scale + lane * 8);
        float4 sc1 = *(const float4*)(ln_scale + lane * 8 + 4);
        float4 of0 = *(const float4*)(ln_offset + lane * 8);
        float4 of1 = *(const float4*)(ln_offset + lane * 8 + 4);
        float y[8];
        y[0] = (x0.x - mu) * rstd * sc0.x + of0.x;
        y[1] = (x0.y - mu) * rstd * sc0.y + of0.y;
        y[2] = (x0.z - mu) * rstd * sc0.z + of0.z;
        y[3] = (x0.w - mu) * rstd * sc0.w + of0.w;
        y[4] = (x1.x - mu) * rstd * sc1.x + of1.x;
        y[5] = (x1.y - mu) * rstd * sc1.y + of1.y;
        y[6] = (x1.z - mu) * rstd * sc1.z + of1.z;
        y[7] = (x1.w - mu) * rstd * sc1.w + of1.w;
        float hi[8];
        uint4 vh, vl;
        #pragma unroll
        for (int j = 0; j < 8; j++)
            hi[j] = __half2float(__float2half_rn(y[j]));
        vh.x = pack_h2(y[0], y[1]); vh.y = pack_h2(y[2], y[3]);
        vh.z = pack_h2(y[4], y[5]); vh.w = pack_h2(y[6], y[7]);
        vl.x = pack_h2(y[0]-hi[0], y[1]-hi[1]); vl.y = pack_h2(y[2]-hi[2], y[3]-hi[3]);
        vl.z = pack_h2(y[4]-hi[4], y[5]-hi[5]); vl.w = pack_h2(y[6]-hi[6], y[7]-hi[7]);
        uint32_t off = (lane >> 2) * YT_STRIDE + swz(rl, lane & 3);
        *(uint4*)(smem + LNP_YHI + off) = vh;
        *(uint4*)(smem + LNP_YLO + off) = vl;
    }
    CP_WAIT(0);
    __syncthreads();

    int m2 = wid & 3, n32 = wid >> 2;
    uint32_t aoff[2], boff[2][2];
    #pragma unroll
    for (int ks = 0; ks < 2; ks++) {
        aoff[ks] = swz(m2 * 16 + (lane & 15), ks * 2 + (lane >> 4));
        #pragma unroll
        for (int n2 = 0; n2 < 2; n2++)
            boff[n2][ks] = swz(n32 * 32 + n2 * 16 + (lane & 15), ks * 2 + (lane >> 4));
    }
    float acc[4][4];
    #pragma unroll
    for (int a = 0; a < 4; a++)
        #pragma unroll
        for (int c = 0; c < 4; c++) acc[a][c] = 0.f;

    #pragma unroll
    for (int kc = 0; kc < 8; kc++) {
        uint32_t yh = sb + LNP_YHI + kc * YT_STRIDE;
        uint32_t yl = sb + LNP_YLO + kc * YT_STRIDE;
        uint32_t wb = sb + LNP_W   + kc * YT_STRIDE;
        #pragma unroll
        for (int ks = 0; ks < 2; ks++) {
            uint32_t ah[4], al[4], b0[4], b1[4];
            LDSM_X4(ah, yh + aoff[ks]);
            LDSM_X4(al, yl + aoff[ks]);
            LDSM_X4(b0, wb + boff[0][ks]);
            LDSM_X4(b1, wb + boff[1][ks]);
            #pragma unroll
            for (int nt = 0; nt < 4; nt++) {
                uint32_t* bp = (nt < 2) ? b0 : b1;
                MMA_F16(acc[nt], ah, bp[nt & 1], bp[(nt & 1) + 2]);
            }
            #pragma unroll
            for (int nt = 0; nt < 4; nt++) {
                uint32_t* bp = (nt < 2) ? b0 : b1;
                MMA_F16(acc[nt], al, bp[nt & 1], bp[(nt & 1) + 2]);
            }
        }
    }

    __half* dstb = n32 ? g_Rh : g_Lh;
    #pragma unroll
    for (int nt = 0; nt < 4; nt++) {
        int ogl = nt * 8 + (lane & 3) * 2;
        float b0v = n32 ? right_b[ogl] : left_b[ogl];
        float b1v = n32 ? right_b[ogl + 1] : left_b[ogl + 1];
        #pragma unroll
        for (int h = 0; h < 2; h++) {
            int a = a0 + m2 * 16 + (lane >> 2) + h * 8;
            float mv = mask[(size_t)a * N_RES + b];
            float vx = mv * (acc[nt][h * 2 + 0] + b0v);
            float vy = mv * (acc[nt][h * 2 + 1] + b1v);
            dstb[(size_t)(b * 32 + ogl)     * N_SEQ + a] = __float2half_rn(vx);
            dstb[(size_t)(b * 32 + ogl + 1) * N_SEQ + a] = __float2half_rn(vy);
        }
    }
}

// ------ prep: norm recip (0..575) + W transpose (576..703) + PwT (704) -----
__global__ __launch_bounds__(256) void prep_kernel(
    const float* __restrict__ mask, const float* __restrict__ W,
    const float* __restrict__ left_w, const float* __restrict__ right_w)
{
    if (blockIdx.x < 576) {
        int m = blockIdx.x * 256 + threadIdx.x;
        int b = m / N_RES, d = m % N_RES;
        float s = 0.f;
        #pragma unroll 4
        for (int a = 0; a < N_SEQ; a++)
            s += mask[a * N_RES + b] * mask[a * N_RES + d];
        g_ninv[m] = 1.0f / (1e-3f + s);
    } else if (blockIdx.x < 704) {
        __shared__ float t[32][33];
        int bb = blockIdx.x - 576;
        int k0 = (bb & 31) * 32;
        int f0 = (bb >> 5) * 32;
        for (int i = threadIdx.x; i < 1024; i += 256) {
            int r = i >> 5, c = i & 31;
            t[r][c] = W[(size_t)(k0 + r) * C_Z + f0 + c];
        }
        __syncthreads();
        for (int i = threadIdx.x; i < 1024; i += 256) {
            int r = i >> 5, c = i & 31;
            g_Wt[(size_t)(f0 + r) * KCE + k0 + c] = __float2half_rn(t[c][r]);
        }
    } else {
        for (int i = 0; i < 64; i++) {
            int og = i, k = threadIdx.x;
            float v = (og < 32) ? left_w[k * C_OUT + og]
                                : right_w[k * C_OUT + og - 32];
            g_PwT[og * C_M + k] = __float2half_rn(v);
        }
    }
}

// ============ GEMM smem geometry ===========================================
#define TILE_B   8192                    /* 128 rows x 64B, XOR-swizzled */
#define G1_STAGE 16384                   /* 2 tiles: Lh, Rh */
#define G1_SMEM  49152                   /* 3 stages; gemm1 epi reuses 32KB */
#define G2_STAGE 16384                   /* 2 tiles: A, Wt */
#define G2_SMEM  65536                   /* 4 stages */

// ---------------- Kernel 3: GEMM1 = L^T R (single-term fp16) ---------------
__global__ __launch_bounds__(256, 2) void gemm1_mma()
{
    extern __shared__ __align__(128) char smem[];
    uint32_t sb = smem_u32(smem);
    int tid = threadIdx.x, lane = tid & 31, wid = tid >> 5;
    int i0 = blockIdx.y * 128;     // bc (M)
    int j0 = blockIdx.x * 128;     // de (N)
    int m_base = (wid & 1) * 64, n_base = (wid >> 1) * 32;

    const __half* base[2] = {
        g_Lh + (size_t)i0 * N_SEQ, g_Rh + (size_t)j0 * N_SEQ };

    uint32_t soff[2]; int gofs[2];
    #pragma unroll
    for (int i = 0; i < 2; i++) {
        int ch = tid + (i << 8);
        int m = ch >> 2, c = ch & 3;
        soff[i] = swz(m, c);
        gofs[i] = m * N_SEQ + c * 8;
    }

    uint32_t aoff[4][2], boff[2][2];
    #pragma unroll
    for (int mt = 0; mt < 4; mt++)
        #pragma unroll
        for (int ks = 0; ks < 2; ks++)
            aoff[mt][ks] = swz(m_base + mt * 16 + (lane & 15), ks * 2 + (lane >> 4));
    #pragma unroll
    for (int n2 = 0; n2 < 2; n2++)
        #pragma unroll
        for (int ks = 0; ks < 2; ks++)
            boff[n2][ks] = swz(n_base + n2 * 16 + (lane & 15), ks * 2 + (lane >> 4));

    float acc[4][4][4];
    #pragma unroll
    for (int a = 0; a < 4; a++)
        #pragma unroll
        for (int b = 0; b < 4; b++)
            #pragma unroll
            for (int c = 0; c < 4; c++) acc[a][b][c] = 0.f;

    #pragma unroll
    for (int s = 0; s < 2; s++) {
        #pragma unroll
        for (int t = 0; t < 2; t++)
            #pragma unroll
            for (int i = 0; i < 2; i++)
                CP_ASYNC16(sb + s * G1_STAGE + t * TILE_B + soff[i],
                           base[t] + gofs[i] + s * 32);
        CP_COMMIT();
    }

    for (int kt = 0; kt < 16; kt++) {
        CP_WAIT(1);
        __syncthreads();
        if (kt + 2 < 16) {
            uint32_t so = (uint32_t)((kt + 2) % 3) * G1_STAGE;
            #pragma unroll
            for (int t = 0; t < 2; t++)
                #pragma unroll
                for (int i = 0; i < 2; i++)
                    CP_ASYNC16(sb + so + t * TILE_B + soff[i],
                               base[t] + gofs[i] + (kt + 2) * 32);
        }
        CP_COMMIT();
        uint32_t stb = sb + (uint32_t)(kt % 3) * G1_STAGE;
        #pragma unroll
        for (int ks = 0; ks < 2; ks++) {
            uint32_t ah[4][4], bh[2][4];
            #pragma unroll
            for (int mt = 0; mt < 4; mt++)
                LDSM_X4(ah[mt], stb + aoff[mt][ks]);
            #pragma unroll
            for (int n2 = 0; n2 < 2; n2++)
                LDSM_X4(bh[n2], stb + TILE_B + boff[n2][ks]);
            #pragma unroll
            for (int mt = 0; mt < 4; mt++)
                #pragma unroll
                for (int nt = 0; nt < 4; nt++)
                    MMA_F16(acc[mt][nt], ah[mt], bh[nt >> 1][nt & 1],
                            bh[nt >> 1][(nt & 1) + 2]);
        }
    }

    // epilogue: scatter into smem (single fp16, permuted), then coalesced copy
    __syncthreads();
    int g = lane >> 2, tg = lane & 3;
    #pragma unroll
    for (int mt = 0; mt < 4; mt++) {
        #pragma unroll
        for (int h = 0; h < 2; h++) {
            int rr = m_base + mt * 16 + g + h * 8;
            int bl = rr >> 5, c = rr & 31;
            #pragma unroll
            for (int nt = 0; nt < 4; nt++) {
                int q = n_base + nt * 8 + tg * 2;
                int dl = q >> 5, e = q & 31;
                int p = bl * 4 + dl;
                uint32_t off = (uint32_t)(p * 2048 + (c * 32 + e) * 2);
                *(__half2*)(smem + off) = __halves2half2(
                    __float2half_rn(acc[mt][nt][h * 2 + 0]),
                    __float2half_rn(acc[mt][nt][h * 2 + 1]));
            }
        }
    }
    __syncthreads();
    int b0 = blockIdx.y * 4, d0 = blockIdx.x * 4;
    #pragma unroll
    for (int i = 0; i < 8; i++) {
        int qc = tid + 256 * i;
        int p = qc >> 7, off = qc & 127;
        size_t row = (size_t)((b0 + (p >> 2)) * N_RES + d0 + (p & 3)) * KCE + off * 8;
        *(uint4*)(g_iPhi + row) = *(const uint4*)(smem + qc * 16);
    }
}

// ---------------- Kernel 4: GEMM2 = interP @ Wt^T + b, / norm (1-term) -----
// 4-stage pipeline to cover DRAM latency on the streaming A read.
__global__ __launch_bounds__(256, 2) void gemm2_mma(
    const float* __restrict__ ob, float* __restrict__ out)
{
    extern __shared__ __align__(128) char smem[];
    uint32_t sb = smem_u32(smem);
    int tid = threadIdx.x, lane = tid & 31, wid = tid >> 5;
    int m0 = blockIdx.x * 128;
    int m_base = (wid & 1) * 64, n_base = (wid >> 1) * 32;

    const __half* base[2] = { g_iPhi + (size_t)m0 * KCE, g_Wt };

    uint32_t soff[2]; int gofs[2];
    #pragma unroll
    for (int i = 0; i < 2; i++) {
        int ch = tid + (i << 8);
        int m = ch >> 2, c = ch & 3;
        soff[i] = swz(m, c);
        gofs[i] = m * KCE + c * 8;
    }

    uint32_t aoff[4][2], boff[2][2];
    #pragma unroll
    for (int mt = 0; mt < 4; mt++)
        #pragma unroll
        for (int ks = 0; ks < 2; ks++)
            aoff[mt][ks] = swz(m_base + mt * 16 + (lane & 15), ks * 2 + (lane >> 4));
    #pragma unroll
    for (int n2 = 0; n2 < 2; n2++)
        #pragma unroll
        for (int ks = 0; ks < 2; ks++)
            boff[n2][ks] = swz(n_base + n2 * 16 + (lane & 15), ks * 2 + (lane >> 4));

    float acc[4][4][4];
    #pragma unroll
    for (int a = 0; a < 4; a++)
        #pragma unroll
        for (int b = 0; b < 4; b++)
            #pragma unroll
            for (int c = 0; c < 4; c++) acc[a][b][c] = 0.f;

    // prologue: fill stages 0..2
    #pragma unroll
    for (int s = 0; s < 3; s++) {
        #pragma unroll
        for (int t = 0; t < 2; t++)
            #pragma unroll
            for (int i = 0; i < 2; i++)
                CP_ASYNC16(sb + s * G2_STAGE + t * TILE_B + soff[i],
                           base[t] + gofs[i] + s * 32);
        CP_COMMIT();
    }

    for (int kt = 0; kt < 32; kt++) {
        CP_WAIT(2);
        __syncthreads();
        if (kt + 3 < 32) {
            uint32_t so = (uint32_t)((kt + 3) & 3) * G2_STAGE;
            #pragma unroll
            for (int t = 0; t < 2; t++)
                #pragma unroll
                for (int i = 0; i < 2; i++)
                    CP_ASYNC16(sb + so + t * TILE_B + soff[i],
                               base[t] + gofs[i] + (kt + 3) * 32);
        }
        CP_COMMIT();   // always commit: uniform group accounting
        uint32_t stb = sb + (uint32_t)(kt & 3) * G2_STAGE;
        #pragma unroll
        for (int ks = 0; ks < 2; ks++) {
            uint32_t ah[4][4], bh[2][4];
            #pragma unroll
            for (int mt = 0; mt < 4; mt++)
                LDSM_X4(ah[mt], stb + aoff[mt][ks]);
            #pragma unroll
            for (int n2 = 0; n2 < 2; n2++)
                LDSM_X4(bh[n2], stb + TILE_B + boff[n2][ks]);
            #pragma unroll
            for (int mt = 0; mt < 4; mt++)
                #pragma unroll
                for (int nt = 0; nt < 4; nt++)
                    MMA_F16(acc[mt][nt], ah[mt], bh[nt >> 1][nt & 1],
                            bh[nt >> 1][(nt & 1) + 2]);
        }
    }

    int g = lane >> 2, tg = lane & 3;
    #pragma unroll
    for (int mt = 0; mt < 4; mt++) {
        #pragma unroll
        for (int h = 0; h < 2; h++) {
            int m = m0 + m_base + mt * 16 + g + h * 8;
            float inv = g_ninv[m];
            #pragma unroll
            for (int nt = 0; nt < 4; nt++) {
                int f = n_base + nt * 8 + tg * 2;
                float2 v;
                v.x = (acc[mt][nt][h * 2 + 0] + ob[f + 0]) * inv;
                v.y = (acc[mt][nt][h * 2 + 1] + ob[f + 1]) * inv;
                *(float2*)&out[(size_t)m * C_Z + f] = v;
            }
        }
    }
}

// ---------------------------------------------------------------------------
extern "C" void kernel_launch(void* const* d_in, const int* in_sizes, int n_in,
                              void* d_out, int out_size)
{
    const float* act       = (const float*)d_in[0];
    const float* mask      = (const float*)d_in[1];
    const float* ln_scale  = (const float*)d_in[2];
    const float* ln_offset = (const float*)d_in[3];
    const float* left_w    = (const float*)d_in[4];
    const float* left_b    = (const float*)d_in[5];
    const float* right_w   = (const float*)d_in[6];
    const float* right_b   = (const float*)d_in[7];
    const float* output_w  = (const float*)d_in[8];
    const float* output_b  = (const float*)d_in[9];
    float* out = (float*)d_out;

    cudaFuncSetAttribute(ln_proj_mma, cudaFuncAttributeMaxDynamicSharedMemorySize, LNP_SMEM);
    cudaFuncSetAttribute(gemm1_mma, cudaFuncAttributeMaxDynamicSharedMemorySize, G1_SMEM);
    cudaFuncSetAttribute(gemm2_mma, cudaFuncAttributeMaxDynamicSharedMemorySize, G2_SMEM);

    // launches: prep(1), ln_proj_mma(2), gemm1(3), gemm2(4 = profiler slot)
    prep_kernel<<<705, 256>>>(mask, output_w, left_w, right_w);
    ln_proj_mma<<<N_SEQ * N_RES / 64, 256, LNP_SMEM>>>(act, mask, ln_scale, ln_offset,
                                                       left_b, right_b);
    gemm1_mma<<<dim3(BC / 128, BC / 128), 256, G1_SMEM>>>();
    gemm2_mma<<<NPAIR / 128, 256, G2_SMEM>>>(output_b, out);
}

// round 16
// speedup vs baseline: 1.1879x; 1.0407x over previous
#include <cuda_runtime.h>
#include <cuda_fp16.h>
#include <math.h>
#include <stdint.h>

#define N_SEQ 512
#define N_RES 384
#define C_M   256
#define C_OUT 32
#define C_Z   128
#define BC    (N_RES * C_OUT)     /* 12288  (b,c) flattened */
#define NPAIR (N_RES * N_RES)     /* 147456 (b,d) pairs     */
#define KCE   (C_OUT * C_OUT)     /* 1024   (c,e) flattened */

// ---------------- scratch (device globals; no allocation allowed) ----------
__device__ float g_ninv[NPAIR];
__device__ __align__(128) __half g_Lh[(size_t)BC * N_SEQ];
__device__ __align__(128) __half g_Rh[(size_t)BC * N_SEQ];
__device__ __align__(128) __half g_iPhi[(size_t)NPAIR * KCE];  // 302 MB
__device__ __align__(128) __half g_Wt[(size_t)C_Z * KCE];
__device__ __align__(128) __half g_PwT[64 * C_M];

// ======================= PTX helpers =======================================
__device__ __forceinline__ uint32_t smem_u32(const void* p) {
    uint32_t a;
    asm("{ .reg .u64 t; cvta.to.shared.u64 t, %1; cvt.u32.u64 %0, t; }"
        : "=r"(a) : "l"(p));
    return a;
}
#define LDSM_X4(r, addr) \
    asm volatile("ldmatrix.sync.aligned.m8n8.x4.shared.b16 {%0,%1,%2,%3}, [%4];" \
                 : "=r"((r)[0]), "=r"((r)[1]), "=r"((r)[2]), "=r"((r)[3]) \
                 : "r"(addr))
#define MMA_F16(d, a, b0, b1) \
    asm volatile("mma.sync.aligned.m16n8k16.row.col.f32.f16.f16.f32 " \
                 "{%0,%1,%2,%3},{%4,%5,%6,%7},{%8,%9},{%0,%1,%2,%3};" \
                 : "+f"((d)[0]), "+f"((d)[1]), "+f"((d)[2]), "+f"((d)[3]) \
                 : "r"((a)[0]), "r"((a)[1]), "r"((a)[2]), "r"((a)[3]), \
                   "r"(b0), "r"(b1))
#define CP_ASYNC16(dst, src) \
    asm volatile("cp.async.cg.shared.global [%0], [%1], 16;" \
                 :: "r"(dst), "l"(src) : "memory")
#define CP_COMMIT() asm volatile("cp.async.commit_group;" ::: "memory")
#define CP_WAIT(n)  asm volatile("cp.async.wait_group %0;" :: "n"(n) : "memory")

// generic XOR swizzle on linear 16B-chunk id L within a tile
__device__ __forceinline__ uint32_t swzL(int L) {
    return (uint32_t)(((L >> 3) << 7) + ((((L & 7) ^ ((L >> 3) & 7))) << 4));
}
// 64B-row tiles (4 chunks/row): L = m*4 + c
__device__ __forceinline__ uint32_t swz(int m, int c) { return swzL(m * 4 + c); }

__device__ __forceinline__ uint32_t pack_h2(float a, float b) {
    __half2 p = __halves2half2(__float2half_rn(a), __float2half_rn(b));
    return *(uint32_t*)&p;
}

// ---------------- Kernel 1: LN + projection via tensor cores ---------------
#define YT_STRIDE 4112
#define LNP_YHI 0
#define LNP_YLO 32896
#define LNP_W   65792
#define LNP_SMEM 98688

__global__ __launch_bounds__(256, 2) void ln_proj_mma(
    const float* __restrict__ act, const float* __restrict__ mask,
    const float* __restrict__ ln_scale, const float* __restrict__ ln_offset,
    const float* __restrict__ left_b, const float* __restrict__ right_b)
{
    extern __shared__ __align__(128) char smem[];
    uint32_t sb = smem_u32(smem);
    int tid = threadIdx.x, lane = tid & 31, wid = tid >> 5;
    int b  = blockIdx.x % N_RES;
    int a0 = (blockIdx.x / N_RES) * 64;

    #pragma unroll
    for (int i = 0; i < 8; i++) {
        int q = tid * 8 + i;
        int row = q >> 5, c32 = q & 31;
        CP_ASYNC16(sb + LNP_W + (c32 >> 2) * YT_STRIDE + swz(row, c32 & 3),
                   g_PwT + row * C_M + c32 * 8);
    }
    CP_COMMIT();

    for (int it = 0; it < 8; it++) {
        int rl = wid + it * 8;
        size_t row = (size_t)(a0 + rl) * N_RES + b;
        const float4* ap = (const float4*)(act + row * C_M + lane * 8);
        float4 x0 = ap[0], x1 = ap[1];
        float s  = x0.x + x0.y + x0.z + x0.w + x1.x + x1.y + x1.z + x1.w;
        float s2 = x0.x*x0.x + x0.y*x0.y + x0.z*x0.z + x0.w*x0.w
                 + x1.x*x1.x + x1.y*x1.y + x1.z*x1.z + x1.w*x1.w;
        #pragma unroll
        for (int o = 16; o > 0; o >>= 1) {
            s  += __shfl_xor_sync(0xffffffffu, s, o);
            s2 += __shfl_xor_sync(0xffffffffu, s2, o);
        }
        float mu = s * (1.0f / C_M);
        float var = s2 * (1.0f / C_M) - mu * mu;
        float rstd = rsqrtf(var + 1e-5f);
        float4 sc0 = *(const float4*)(ln_scale + lane * 8);
        float4 sc1 = *(const float4*)(ln_scale + lane * 8 + 4);
        float4 of0 = *(const float4*)(ln_offset + lane * 8);
        float4 of1 = *(const float4*)(ln_offset + lane * 8 + 4);
        float y[8];
        y[0] = (x0.x - mu) * rstd * sc0.x + of0.x;
        y[1] = (x0.y - mu) * rstd * sc0.y + of0.y;
        y[2] = (x0.z - mu) * rstd * sc0.z + of0.z;
        y[3] = (x0.w - mu) * rstd * sc0.w + of0.w;
        y[4] = (x1.x - mu) * rstd * sc1.x + of1.x;
        y[5] = (x1.y - mu) * rstd * sc1.y + of1.y;
        y[6] = (x1.z - mu) * rstd * sc1.z + of1.z;
        y[7] = (x1.w - mu) * rstd * sc1.w + of1.w;
        float hi[8];
        uint4 vh, vl;
        #pragma unroll
        for (int j = 0; j < 8; j++)
            hi[j] = __half2float(__float2half_rn(y[j]));
        vh.x = pack_h2(y[0], y[1]); vh.y = pack_h2(y[2], y[3]);
        vh.z = pack_h2(y[4], y[5]); vh.w = pack_h2(y[6], y[7]);
        vl.x = pack_h2(y[0]-hi[0], y[1]-hi[1]); vl.y = pack_h2(y[2]-hi[2], y[3]-hi[3]);
        vl.z = pack_h2(y[4]-hi[4], y[5]-hi[5]); vl.w = pack_h2(y[6]-hi[6], y[7]-hi[7]);
        uint32_t off = (lane >> 2) * YT_STRIDE + swz(rl, lane & 3);
        *(uint4*)(smem + LNP_YHI + off) = vh;
        *(uint4*)(smem + LNP_YLO + off) = vl;
    }
    CP_WAIT(0);
    __syncthreads();

    int m2 = wid & 3, n32 = wid >> 2;
    uint32_t aoff[2], boff[2][2];
    #pragma unroll
    for (int ks = 0; ks < 2; ks++) {
        aoff[ks] = swz(m2 * 16 + (lane & 15), ks * 2 + (lane >> 4));
        #pragma unroll
        for (int n2 = 0; n2 < 2; n2++)
            boff[n2][ks] = swz(n32 * 32 + n2 * 16 + (lane & 15), ks * 2 + (lane >> 4));
    }
    float acc[4][4];
    #pragma unroll
    for (int a = 0; a < 4; a++)
        #pragma unroll
        for (int c = 0; c < 4; c++) acc[a][c] = 0.f;

    #pragma unroll
    for (int kc = 0; kc < 8; kc++) {
        uint32_t yh = sb + LNP_YHI + kc * YT_STRIDE;
        uint32_t yl = sb + LNP_YLO + kc * YT_STRIDE;
        uint32_t wb = sb + LNP_W   + kc * YT_STRIDE;
        #pragma unroll
        for (int ks = 0; ks < 2; ks++) {
            uint32_t ah[4], al[4], b0[4], b1[4];
            LDSM_X4(ah, yh + aoff[ks]);
            LDSM_X4(al, yl + aoff[ks]);
            LDSM_X4(b0, wb + boff[0][ks]);
            LDSM_X4(b1, wb + boff[1][ks]);
            #pragma unroll
            for (int nt = 0; nt < 4; nt++) {
                uint32_t* bp = (nt < 2) ? b0 : b1;
                MMA_F16(acc[nt], ah, bp[nt & 1], bp[(nt & 1) + 2]);
            }
            #pragma unroll
            for (int nt = 0; nt < 4; nt++) {
                uint32_t* bp = (nt < 2) ? b0 : b1;
                MMA_F16(acc[nt], al, bp[nt & 1], bp[(nt & 1) + 2]);
            }
        }
    }

    __half* dstb = n32 ? g_Rh : g_Lh;
    #pragma unroll
    for (int nt = 0; nt < 4; nt++) {
        int ogl = nt * 8 + (lane & 3) * 2;
        float b0v = n32 ? right_b[ogl] : left_b[ogl];
        float b1v = n32 ? right_b[ogl + 1] : left_b[ogl + 1];
        #pragma unroll
        for (int h = 0; h < 2; h++) {
            int a = a0 + m2 * 16 + (lane >> 2) + h * 8;
            float mv = mask[(size_t)a * N_RES + b];
            float vx = mv * (acc[nt][h * 2 + 0] + b0v);
            float vy = mv * (acc[nt][h * 2 + 1] + b1v);
            dstb[(size_t)(b * 32 + ogl)     * N_SEQ + a] = __float2half_rn(vx);
            dstb[(size_t)(b * 32 + ogl + 1) * N_SEQ + a] = __float2half_rn(vy);
        }
    }
}

// ------ prep: norm recip (0..575) + W transpose (576..703) + PwT (704) -----
__global__ __launch_bounds__(256) void prep_kernel(
    const float* __restrict__ mask, const float* __restrict__ W,
    const float* __restrict__ left_w, const float* __restrict__ right_w)
{
    if (blockIdx.x < 576) {
        int m = blockIdx.x * 256 + threadIdx.x;
        int b = m / N_RES, d = m % N_RES;
        float s = 0.f;
        for (int a = 0; a < N_SEQ; a++)
            s += mask[a * N_RES + b] * mask[a * N_RES + d];
        g_ninv[m] = 1.0f / (1e-3f + s);
    } else if (blockIdx.x < 704) {
        __shared__ float t[32][33];
        int bb = blockIdx.x - 576;
        int k0 = (bb & 31) * 32;
        int f0 = (bb >> 5) * 32;
        for (int i = threadIdx.x; i < 1024; i += 256) {
            int r = i >> 5, c = i & 31;
            t[r][c] = W[(size_t)(k0 + r) * C_Z + f0 + c];
        }
        __syncthreads();
        for (int i = threadIdx.x; i < 1024; i += 256) {
            int r = i >> 5, c = i & 31;
            g_Wt[(size_t)(f0 + r) * KCE + k0 + c] = __float2half_rn(t[c][r]);
        }
    } else {
        for (int i = 0; i < 64; i++) {
            int og = i, k = threadIdx.x;
            float v = (og < 32) ? left_w[k * C_OUT + og]
                                : right_w[k * C_OUT + og - 32];
            g_PwT[og * C_M + k] = __float2half_rn(v);
        }
    }
}

// ============ GEMM1: KC=64 (128B rows), 3 stages, 8 syncs ==================
#define T1B      16384                   /* tile: 128 rows x 128B */
#define G1_STAGE 32768                   /* 2 tiles */
#define G1_SMEM  98304                   /* 3 stages; epilogue reuses 32KB */

__global__ __launch_bounds__(256, 2) void gemm1_mma()
{
    extern __shared__ __align__(128) char smem[];
    uint32_t sb = smem_u32(smem);
    int tid = threadIdx.x, lane = tid & 31, wid = tid >> 5;
    int i0 = blockIdx.y * 128;     // bc (M)
    int j0 = blockIdx.x * 128;     // de (N)
    int m_base = (wid & 1) * 64, n_base = (wid >> 1) * 32;

    const __half* Ab = g_Lh + (size_t)i0 * N_SEQ;
    const __half* Bb = g_Rh + (size_t)j0 * N_SEQ;

    // LDSM address decomposition: phys = (r<<7) + ((c ^ (r&7))<<4), c = 2ks+h
    int h = lane >> 4;
    uint32_t aB[4], aP[4], bB[2], bP[2];
    #pragma unroll
    for (int mt = 0; mt < 4; mt++) {
        int r = m_base + mt * 16 + (lane & 15);
        aB[mt] = (uint32_t)((r << 7) + (((h ^ (r & 1))) << 4));
        aP[mt] = (uint32_t)((r & 6) << 4);
    }
    #pragma unroll
    for (int n2 = 0; n2 < 2; n2++) {
        int r = n_base + n2 * 16 + (lane & 15);
        bB[n2] = (uint32_t)(T1B + (r << 7) + (((h ^ (r & 1))) << 4));
        bP[n2] = (uint32_t)((r & 6) << 4);
    }

    float acc[4][4][4];
    #pragma unroll
    for (int a = 0; a < 4; a++)
        #pragma unroll
        for (int b = 0; b < 4; b++)
            #pragma unroll
            for (int c = 0; c < 4; c++) acc[a][b][c] = 0.f;

    // prologue: stages 0,1 (K chunks 0,1); 8 chunks of 16B per thread/stage
    #pragma unroll
    for (int s = 0; s < 2; s++) {
        #pragma unroll
        for (int i = 0; i < 8; i++) {
            int ch = tid + (i << 8);          // 0..2047
            int L = ch & 1023;
            const __half* g = ((i < 4) ? Ab : Bb)
                              + (size_t)(L >> 3) * N_SEQ + (L & 7) * 8 + s * 64;
            uint32_t d = sb + s * G1_STAGE + ((i < 4) ? 0u : (uint32_t)T1B) + swzL(L);
            CP_ASYNC16(d, g);
        }
        CP_COMMIT();
    }

    for (int kt = 0; kt < 8; kt++) {
        CP_WAIT(1);
        __syncthreads();
        if (kt + 2 < 8) {
            uint32_t so = (uint32_t)((kt + 2) % 3) * G1_STAGE;
            #pragma unroll
            for (int i = 0; i < 8; i++) {
                int ch = tid + (i << 8);
                int L = ch & 1023;
                const __half* g = ((i < 4) ? Ab : Bb)
                                  + (size_t)(L >> 3) * N_SEQ + (L & 7) * 8 + (kt + 2) * 64;
                uint32_t d = sb + so + ((i < 4) ? 0u : (uint32_t)T1B) + swzL(L);
                CP_ASYNC16(d, g);
            }
        }
        CP_COMMIT();
        uint32_t stb = sb + (uint32_t)(kt % 3) * G1_STAGE;
        #pragma unroll
        for (int ks = 0; ks < 4; ks++) {
            uint32_t kx = (uint32_t)(ks << 5);
            uint32_t ah[4][4], bh[2][4];
            #pragma unroll
            for (int mt = 0; mt < 4; mt++)
                LDSM_X4(ah[mt], stb + aB[mt] + (kx ^ aP[mt]));
            #pragma unroll
            for (int n2 = 0; n2 < 2; n2++)
                LDSM_X4(bh[n2], stb + bB[n2] + (kx ^ bP[n2]));
            #pragma unroll
            for (int mt = 0; mt < 4; mt++)
                #pragma unroll
                for (int nt = 0; nt < 4; nt++)
                    MMA_F16(acc[mt][nt], ah[mt], bh[nt >> 1][nt & 1],
                            bh[nt >> 1][(nt & 1) + 2]);
        }
    }

    // epilogue: scatter into smem (single fp16, permuted), then coalesced copy
    __syncthreads();
    int g = lane >> 2, tg = lane & 3;
    #pragma unroll
    for (int mt = 0; mt < 4; mt++) {
        #pragma unroll
        for (int hh = 0; hh < 2; hh++) {
            int rr = m_base + mt * 16 + g + hh * 8;
            int bl = rr >> 5, c = rr & 31;
            #pragma unroll
            for (int nt = 0; nt < 4; nt++) {
                int q = n_base + nt * 8 + tg * 2;
                int dl = q >> 5, e = q & 31;
                int p = bl * 4 + dl;
                uint32_t off = (uint32_t)(p * 2048 + (c * 32 + e) * 2);
                *(__half2*)(smem + off) = __halves2half2(
                    __float2half_rn(acc[mt][nt][hh * 2 + 0]),
                    __float2half_rn(acc[mt][nt][hh * 2 + 1]));
            }
        }
    }
    __syncthreads();
    int b0 = blockIdx.y * 4, d0 = blockIdx.x * 4;
    #pragma unroll
    for (int i = 0; i < 8; i++) {
        int qc = tid + 256 * i;
        int p = qc >> 7, off = qc & 127;
        size_t row = (size_t)((b0 + (p >> 2)) * N_RES + d0 + (p & 3)) * KCE + off * 8;
        *(uint4*)(g_iPhi + row) = *(const uint4*)(smem + qc * 16);
    }
}

// ============ GEMM2: 4-stage (proven R15 win) ==============================
#define TILE_B   8192
#define G2_STAGE 16384
#define G2_SMEM  65536

__global__ __launch_bounds__(256, 2) void gemm2_mma(
    const float* __restrict__ ob, float* __restrict__ out)
{
    extern __shared__ __align__(128) char smem[];
    uint32_t sb = smem_u32(smem);
    int tid = threadIdx.x, lane = tid & 31, wid = tid >> 5;
    int m0 = blockIdx.x * 128;
    int m_base = (wid & 1) * 64, n_base = (wid >> 1) * 32;

    const __half* base[2] = { g_iPhi + (size_t)m0 * KCE, g_Wt };

    uint32_t soff[2]; int gofs[2];
    #pragma unroll
    for (int i = 0; i < 2; i++) {
        int ch = tid + (i << 8);
        int m = ch >> 2, c = ch & 3;
        soff[i] = swz(m, c);
        gofs[i] = m * KCE + c * 8;
    }

    uint32_t aoff[4][2], boff[2][2];
    #pragma unroll
    for (int mt = 0; mt < 4; mt++)
        #pragma unroll
        for (int ks = 0; ks < 2; ks++)
            aoff[mt][ks] = swz(m_base + mt * 16 + (lane & 15), ks * 2 + (lane >> 4));
    #pragma unroll
    for (int n2 = 0; n2 < 2; n2++)
        #pragma unroll
        for (int ks = 0; ks < 2; ks++)
            boff[n2][ks] = swz(n_base + n2 * 16 + (lane & 15), ks * 2 + (lane >> 4));

    float acc[4][4][4];
    #pragma unroll
    for (int a = 0; a < 4; a++)
        #pragma unroll
        for (int b = 0; b < 4; b++)
            #pragma unroll
            for (int c = 0; c < 4; c++) acc[a][b][c] = 0.f;

    #pragma unroll
    for (int s = 0; s < 3; s++) {
        #pragma unroll
        for (int t = 0; t < 2; t++)
            #pragma unroll
            for (int i = 0; i < 2; i++)
                CP_ASYNC16(sb + s * G2_STAGE + t * TILE_B + soff[i],
                           base[t] + gofs[i] + s * 32);
        CP_COMMIT();
    }

    for (int kt = 0; kt < 32; kt++) {
        CP_WAIT(2);
        __syncthreads();
        if (kt + 3 < 32) {
            uint32_t so = (uint32_t)((kt + 3) & 3) * G2_STAGE;
            #pragma unroll
            for (int t = 0; t < 2; t++)
                #pragma unroll
                for (int i = 0; i < 2; i++)
                    CP_ASYNC16(sb + so + t * TILE_B + soff[i],
                               base[t] + gofs[i] + (kt + 3) * 32);
        }
        CP_COMMIT();
        uint32_t stb = sb + (uint32_t)(kt & 3) * G2_STAGE;
        #pragma unroll
        for (int ks = 0; ks < 2; ks++) {
            uint32_t ah[4][4], bh[2][4];
            #pragma unroll
            for (int mt = 0; mt < 4; mt++)
                LDSM_X4(ah[mt], stb + aoff[mt][ks]);
            #pragma unroll
            for (int n2 = 0; n2 < 2; n2++)
                LDSM_X4(bh[n2], stb + TILE_B + boff[n2][ks]);
            #pragma unroll
            for (int mt = 0; mt < 4; mt++)
                #pragma unroll
                for (int nt = 0; nt < 4; nt++)
                    MMA_F16(acc[mt][nt], ah[mt], bh[nt >> 1][nt & 1],
                            bh[nt >> 1][(nt & 1) + 2]);
        }
    }

    int g = lane >> 2, tg = lane & 3;
    #pragma unroll
    for (int mt = 0; mt < 4; mt++) {
        #pragma unroll
        for (int h = 0; h < 2; h++) {
            int m = m0 + m_base + mt * 16 + g + h * 8;
            float inv = g_ninv[m];
            #pragma unroll
            for (int nt = 0; nt < 4; nt++) {
                int f = n_base + nt * 8 + tg * 2;
                float2 v;
                v.x = (acc[mt][nt][h * 2 + 0] + ob[f + 0]) * inv;
                v.y = (acc[mt][nt][h * 2 + 1] + ob[f + 1]) * inv;
                *(float2*)&out[(size_t)m * C_Z + f] = v;
            }
        }
    }
}

// ---------------------------------------------------------------------------
extern "C" void kernel_launch(void* const* d_in, const int* in_sizes, int n_in,
                              void* d_out, int out_size)
{
    const float* act       = (const float*)d_in[0];
    const float* mask      = (const float*)d_in[1];
    const float* ln_scale  = (const float*)d_in[2];
    const float* ln_offset = (const float*)d_in[3];
    const float* left_w    = (const float*)d_in[4];
    const float* left_b    = (const float*)d_in[5];
    const float* right_w   = (const float*)d_in[6];
    const float* right_b   = (const float*)d_in[7];
    const float* output_w  = (const float*)d_in[8];
    const float* output_b  = (const float*)d_in[9];
    float* out = (float*)d_out;

    cudaFuncSetAttribute(ln_proj_mma, cudaFuncAttributeMaxDynamicSharedMemorySize, LNP_SMEM);
    cudaFuncSetAttribute(gemm1_mma, cudaFuncAttributeMaxDynamicSharedMemorySize, G1_SMEM);
    cudaFuncSetAttribute(gemm2_mma, cudaFuncAttributeMaxDynamicSharedMemorySize, G2_SMEM);

    // launches: prep(1), ln_proj_mma(2), gemm1(3), gemm2(4 = profiler slot)
    prep_kernel<<<705, 256>>>(mask, output_w, left_w, right_w);
    ln_proj_mma<<<N_SEQ * N_RES / 64, 256, LNP_SMEM>>>(act, mask, ln_scale, ln_offset,
                                                       left_b, right_b);
    gemm1_mma<<<dim3(BC / 128, BC / 128), 256, G1_SMEM>>>();
    gemm2_mma<<<NPAIR / 128, 256, G2_SMEM>>>(output_b, out);
}